// round 10
// baseline (speedup 1.0000x reference)
#include <cuda_runtime.h>
#include <math.h>

// Problem constants
#define Hd 512
#define L 4096
#define B 8
#define N2 32
#define HN (Hd * N2)
#define T 64            // chunk length
#define NCH (L / T)     // 64 chunks per sequence
#define CB (NCH * B)    // 512 chunk-rows
#define Q 64            // 2*N2 (re block + im block)
#define BL (B * L)      // 32768
#define CBP 516         // padded locS row stride (floats)
#define XRP 132         // padded xrs row stride

typedef unsigned long long u64;

__device__ __forceinline__ u64 pk2(float lo, float hi) {
    u64 r; asm("mov.b64 %0, {%1, %2};" : "=l"(r) : "f"(lo), "f"(hi)); return r;
}
__device__ __forceinline__ float2 upk2(u64 v) {
    float2 f; asm("mov.b64 {%0, %1}, %2;" : "=f"(f.x), "=f"(f.y) : "l"(v)); return f;
}
__device__ __forceinline__ u64 fma2(u64 a, u64 b, u64 c) {
    u64 d; asm("fma.rn.f32x2 %0, %1, %2, %3;" : "=l"(d) : "l"(a), "l"(b), "l"(c)); return d;
}

// ---------------------------------------------------------------------------
// Device-global parameter / scratch arrays
// ---------------------------------------------------------------------------
__device__ float g_C2re[HN], g_C2imN[HN];
__device__ float g_dATre[HN], g_dATim[HN];                  // dA^T (double-derived)
__device__ __align__(16) float g_E[Hd * T * Q];             // [h][tau][q]: dA^{T-1-tau} dB
__device__ __align__(16) float g_Wt[Hd * T * Q];            // [h][t][q] (prep output)
__device__ __align__(16) float g_W[Hd * Q * T];             // [h][q][t] (transposed)
__device__ float g_K[Hd * T];                               // conv kernel
__device__ __align__(16) float g_xT[(size_t)Hd * BL];       // transposed x: [h][b*L+t]
__device__ __align__(16) float g_loc[(size_t)Hd * Q * CB];  // [h][q][cb]
__device__ __align__(16) float g_corr[(size_t)Hd * CB * T]; // [h][cb][t]

// ---------------------------------------------------------------------------
// K0: per-(h,n) discretization + E/Wt tables
// ---------------------------------------------------------------------------
__global__ void k_prep(const float* __restrict__ log_dt,
                       const float* __restrict__ arl,
                       const float* __restrict__ aim,
                       const float* __restrict__ Bre,
                       const float* __restrict__ Bim,
                       const float* __restrict__ Cre,
                       const float* __restrict__ Cim) {
    int i = blockIdx.x * blockDim.x + threadIdx.x;
    if (i >= HN) return;
    int h = i >> 5, n = i & 31;
    float dt   = expf(log_dt[h]);
    float are  = -expf(arl[i]);
    float aimv = aim[i];
    float zre = are * dt, zim = aimv * dt;
    float sz, cz; sincosf(zim, &sz, &cz);
    float ez = expf(zre);
    float dre = ez * cz, dimv = ez * sz;   // dA
    float sh = sinf(0.5f * zim);
    float em1re = expm1f(zre) * cz - 2.0f * sh * sh;
    float em1im = ez * sz;
    float inv = 1.0f / (are * are + aimv * aimv);
    float fre = (em1re * are + em1im * aimv) * inv;
    float fim = (em1im * are - em1re * aimv) * inv;
    float bre0 = Bre[i], bim0 = Bim[i];
    float dbre = bre0 * fre - bim0 * fim;
    float dbim = bre0 * fim + bim0 * fre;
    g_C2re[i]  =  2.0f * Cre[i];
    g_C2imN[i] = -2.0f * Cim[i];
    double zred = (double)are * (double)dt * (double)T;
    double zimd = (double)aimv * (double)dt * (double)T;
    double ezd = exp(zred);
    g_dATre[i] = (float)(ezd * cos(zimd));
    g_dATim[i] = (float)(ezd * sin(zimd));
    // E[tau] = dA^{T-1-tau} dB (reversed rows) ; Wt[t][q] = C dA^{t+1}
    float pre = dbre, pim = dbim;
    float cre0 = Cre[i], cim0 = Cim[i];
    float wre = cre0 * dre - cim0 * dimv;
    float wim = cre0 * dimv + cim0 * dre;
    for (int l = 0; l < T; ++l) {
        g_E[((size_t)h * T + (T - 1 - l)) * Q + n]      = pre;
        g_E[((size_t)h * T + (T - 1 - l)) * Q + 32 + n] = pim;
        g_Wt[((size_t)h * T + l) * Q + n]      =  2.0f * wre;
        g_Wt[((size_t)h * T + l) * Q + 32 + n] = -2.0f * wim;
        float tre = pre * dre - pim * dimv; pim = pre * dimv + pim * dre; pre = tre;
        float ure = wre * dre - wim * dimv; wim = wre * dimv + wim * dre; wre = ure;
    }
}

// K0b: conv kernel K[h][l]
__global__ void k_K() {
    int i = blockIdx.x * blockDim.x + threadIdx.x;
    if (i >= Hd * T) return;
    int h = i >> 6, l = i & 63;
    const float* e   = &g_E[((size_t)h * T + (T - 1 - l)) * Q];
    const float* c2r = &g_C2re[h * 32];
    const float* c2i = &g_C2imN[h * 32];
    float s = 0.0f;
    #pragma unroll 8
    for (int n = 0; n < 32; ++n)
        s = fmaf(c2r[n], e[n], fmaf(c2i[n], e[32 + n], s));
    g_K[i] = s;
}

// K0c: per-h transpose Wt[t][q] -> W[q][t]
__global__ void __launch_bounds__(256) k_wtr() {
    __shared__ float wt[T * 68];
    const int h = blockIdx.x, tid = threadIdx.x;
    for (int k = tid; k < T * Q / 4; k += 256) {
        int t = k >> 4, qq = (k & 15) * 4;
        *reinterpret_cast<float4*>(&wt[t * 68 + qq]) =
            reinterpret_cast<const float4*>(g_Wt + (size_t)h * T * Q)[k];
    }
    __syncthreads();
    for (int k = tid; k < Q * T / 4; k += 256) {
        int q = k >> 4, tq = (k & 15) * 4;
        float4 v = make_float4(wt[(tq + 0) * 68 + q], wt[(tq + 1) * 68 + q],
                               wt[(tq + 2) * 68 + q], wt[(tq + 3) * 68 + q]);
        *reinterpret_cast<float4*>(&g_W[((size_t)h * Q + q) * T + tq]) = v;
    }
}

// ---------------------------------------------------------------------------
// K-tr: transpose x [bt][h] -> xT [h][bt], 64x64 tiles, float4 global I/O
// ---------------------------------------------------------------------------
__global__ void __launch_bounds__(256) k_tr(const float* __restrict__ x) {
    __shared__ float tile[64 * 65];
    const int bt0 = blockIdx.x * 64;
    const int h0  = blockIdx.y * 64;
    const int tid = threadIdx.x;
    #pragma unroll
    for (int it = 0; it < 4; ++it) {
        int idx = tid + it * 256;           // [0,1024)
        int r = idx >> 4, q = idx & 15;
        float4 v = *reinterpret_cast<const float4*>(
            &x[(size_t)(bt0 + r) * Hd + h0 + q * 4]);
        float* tr = &tile[r * 65 + q * 4];
        tr[0] = v.x; tr[1] = v.y; tr[2] = v.z; tr[3] = v.w;
    }
    __syncthreads();
    #pragma unroll
    for (int it = 0; it < 4; ++it) {
        int idx = tid + it * 256;
        int hh = idx >> 4, rq = idx & 15;
        float4 v = make_float4(tile[(rq * 4 + 0) * 65 + hh],
                               tile[(rq * 4 + 1) * 65 + hh],
                               tile[(rq * 4 + 2) * 65 + hh],
                               tile[(rq * 4 + 3) * 65 + hh]);
        *reinterpret_cast<float4*>(&g_xT[(size_t)(h0 + hh) * BL + bt0 + rq * 4]) = v;
    }
}

// ---------------------------------------------------------------------------
// K1: loc[h][q][cb] = sum_tau E[h][tau][q] * x[cb][tau]
// 4 cb per lane, f32x2. grid (Hd, CB/128), block 256, dynamic smem.
// ---------------------------------------------------------------------------
__global__ void __launch_bounds__(256) k_loc() {
    extern __shared__ float sm[];
    float* Es  = sm;                // [64][64] 16KB
    float* xrs = sm + T * Q;        // [64][XRP] 33.8KB
    const int h = blockIdx.x;
    const int cb0 = blockIdx.y * 128;
    const int tid = threadIdx.x;
    for (int k = tid; k < T * Q / 4; k += 256)
        reinterpret_cast<float4*>(Es)[k] =
            reinterpret_cast<const float4*>(g_E + (size_t)h * T * Q)[k];
    for (int k = tid; k < 128 * T; k += 256) {
        int c2 = k >> 6, tau = k & 63;
        int cb = cb0 + c2, b = cb & 7, c = cb >> 3;
        xrs[tau * XRP + c2] = g_xT[(size_t)h * BL + b * L + c * T + tau];
    }
    __syncthreads();
    const int cc = tid & 31, w = tid >> 5, q0 = w * 8;
    u64 acc[4][4];
    #pragma unroll
    for (int a = 0; a < 4; ++a)
        #pragma unroll
        for (int p = 0; p < 4; ++p) acc[a][p] = 0ull;
    #pragma unroll 4
    for (int tau = 0; tau < T; ++tau) {
        float4 xv = *reinterpret_cast<const float4*>(&xrs[tau * XRP + cc * 4]);
        ulonglong2 ea = *reinterpret_cast<const ulonglong2*>(&Es[tau * Q + q0]);
        ulonglong2 eb = *reinterpret_cast<const ulonglong2*>(&Es[tau * Q + q0 + 4]);
        u64 xx;
        xx = pk2(xv.x, xv.x);
        acc[0][0] = fma2(ea.x, xx, acc[0][0]); acc[0][1] = fma2(ea.y, xx, acc[0][1]);
        acc[0][2] = fma2(eb.x, xx, acc[0][2]); acc[0][3] = fma2(eb.y, xx, acc[0][3]);
        xx = pk2(xv.y, xv.y);
        acc[1][0] = fma2(ea.x, xx, acc[1][0]); acc[1][1] = fma2(ea.y, xx, acc[1][1]);
        acc[1][2] = fma2(eb.x, xx, acc[1][2]); acc[1][3] = fma2(eb.y, xx, acc[1][3]);
        xx = pk2(xv.z, xv.z);
        acc[2][0] = fma2(ea.x, xx, acc[2][0]); acc[2][1] = fma2(ea.y, xx, acc[2][1]);
        acc[2][2] = fma2(eb.x, xx, acc[2][2]); acc[2][3] = fma2(eb.y, xx, acc[2][3]);
        xx = pk2(xv.w, xv.w);
        acc[3][0] = fma2(ea.x, xx, acc[3][0]); acc[3][1] = fma2(ea.y, xx, acc[3][1]);
        acc[3][2] = fma2(eb.x, xx, acc[3][2]); acc[3][3] = fma2(eb.y, xx, acc[3][3]);
    }
    #pragma unroll
    for (int p = 0; p < 4; ++p) {
        float2 f0 = upk2(acc[0][p]), f1 = upk2(acc[1][p]);
        float2 f2 = upk2(acc[2][p]), f3 = upk2(acc[3][p]);
        int q = q0 + 2 * p;
        *reinterpret_cast<float4*>(&g_loc[((size_t)h * Q + q) * CB + cb0 + cc * 4]) =
            make_float4(f0.x, f1.x, f2.x, f3.x);
        *reinterpret_cast<float4*>(&g_loc[((size_t)h * Q + q + 1) * CB + cb0 + cc * 4]) =
            make_float4(f0.y, f1.y, f2.y, f3.y);
    }
}

// ---------------------------------------------------------------------------
// K2: fused carry-scan + correction GEMM. One block per h.
// Lane layout for GEMM: lane = (cb quad, t octet) -> direct coalesced stores.
// smem: locS [Q][CBP] + Ws [Q][T]  (148KB)
// ---------------------------------------------------------------------------
__global__ void __launch_bounds__(256) k_corrf(float* __restrict__ out, int stateMode) {
    extern __shared__ float sm[];
    float* locS = sm;                    // 64*516 = 132KB
    float* Ws   = sm + Q * CBP;          // 16KB
    const int h = blockIdx.x;
    const int tid = threadIdx.x;
    for (int k = tid; k < Q * T / 4; k += 256)
        reinterpret_cast<float4*>(Ws)[k] =
            reinterpret_cast<const float4*>(g_W + (size_t)h * Q * T)[k];
    for (int k = tid; k < Q * CB / 4; k += 256) {
        int q = k >> 7, c4 = k & 127;
        *reinterpret_cast<float4*>(&locS[q * CBP + c4 * 4]) =
            reinterpret_cast<const float4*>(g_loc + (size_t)h * Q * CB)[k];
    }
    __syncthreads();
    // exclusive carry scan along chunks, in place; thread = (n, b)
    {
        int n = tid >> 3, b = tid & 7;
        float aRe = g_dATre[h * 32 + n], aIm = g_dATim[h * 32 + n];
        float* pr = &locS[n * CBP + b];
        float* pi = &locS[(32 + n) * CBP + b];
        float cre = 0.0f, cim = 0.0f;
        #pragma unroll 4
        for (int c = 0; c < NCH; ++c) {
            float lre = pr[c * 8], lim = pi[c * 8];
            pr[c * 8] = cre; pi[c * 8] = cim;
            float nre = fmaf(aRe, cre, fmaf(-aIm, cim, lre));
            float nim = fmaf(aIm, cre, fmaf(aRe, cim, lim));
            cre = nre; cim = nim;
        }
        if (stateMode > 0) {
            size_t ysEnd = (size_t)B * L * Hd;
            size_t idx = ((size_t)b * Hd + h) * N2 + n;
            out[ysEnd + idx] = cre;
            if (stateMode > 1) out[ysEnd + (size_t)B * Hd * N2 + idx] = cim;
        }
    }
    __syncthreads();
    // correction GEMM: corr[cb][t] = sum_q W[q][t] * s0[q][cb]
    // lane: cbq = lane>>3 (4 cbs), tg = lane&7 (t octet)
    const int lane = tid & 31, w = tid >> 5;
    const int cbq = lane >> 3, t0 = (lane & 7) * 8;
    #pragma unroll 1
    for (int pass = 0; pass < 16; ++pass) {
        const int cbi = pass * 32 + w * 4 + cbq;
        u64 a0 = 0, a1 = 0, a2 = 0, a3 = 0;
        #pragma unroll 8
        for (int q = 0; q < Q; ++q) {
            float sv = locS[q * CBP + cbi];
            u64 s2 = pk2(sv, sv);
            ulonglong2 wa = *reinterpret_cast<const ulonglong2*>(&Ws[q * T + t0]);
            ulonglong2 wb = *reinterpret_cast<const ulonglong2*>(&Ws[q * T + t0 + 4]);
            a0 = fma2(wa.x, s2, a0); a1 = fma2(wa.y, s2, a1);
            a2 = fma2(wb.x, s2, a2); a3 = fma2(wb.y, s2, a3);
        }
        float2 f0 = upk2(a0), f1 = upk2(a1), f2 = upk2(a2), f3 = upk2(a3);
        float* cp = &g_corr[((size_t)h * CB + cbi) * T + t0];
        *reinterpret_cast<float4*>(cp)     = make_float4(f0.x, f0.y, f1.x, f1.y);
        *reinterpret_cast<float4*>(cp + 4) = make_float4(f2.x, f2.y, f3.x, f3.y);
    }
}

// ---------------------------------------------------------------------------
// K4: output = causal conv(K,x) + corr + D*x, then exact GELU.
// f32x2-packed conv. grid (CB, Hd/32), block 256
// ---------------------------------------------------------------------------
__global__ void __launch_bounds__(256) k_out(const float* __restrict__ x,
                                             const float* __restrict__ Dv,
                                             float* __restrict__ out) {
    __shared__ float xs[32 * 133];
    __shared__ float Ks[32 * 65];
    __shared__ float cs[32 * 65];
    const int cb = blockIdx.x, h0 = blockIdx.y * 32;
    const int b = cb & 7, c = cb >> 3;
    const int tid = threadIdx.x;
    for (int k = tid; k < 32 * 63; k += 256) {
        int hh = k & 31, r = k >> 5;
        xs[hh * 133 + r] = 0.0f;
    }
    for (int k = tid; k < 32 * 64; k += 256) {
        int hh = k & 31, tt = k >> 5;
        xs[hh * 133 + 63 + tt] = x[((size_t)b * L + c * T + tt) * Hd + h0 + hh];
    }
    for (int k = tid; k < 32 * 64; k += 256) {
        int hh = k & 31, l = k >> 5;
        Ks[hh * 65 + l] = g_K[(h0 + hh) * T + l];
    }
    for (int k = tid; k < 2048; k += 256) {
        int hh = k >> 6, tt = k & 63;
        cs[hh * 65 + tt] = g_corr[((size_t)(h0 + hh) * CB + cb) * T + tt];
    }
    __syncthreads();

    const int hh = tid & 31, w = tid >> 5, t0 = w * 8;
    u64 accp[4];
    #pragma unroll
    for (int p = 0; p < 4; ++p)
        accp[p] = pk2(cs[hh * 65 + t0 + 2 * p], cs[hh * 65 + t0 + 2 * p + 1]);

    const float* xrow = &xs[hh * 133];
    const float* krow = &Ks[hh * 65];
    for (int lt = 0; lt <= w; ++lt) {
        const int l0 = lt * 8;
        const int rb = 63 + t0 - l0 - 7;
        float xw[15];
        #pragma unroll
        for (int j = 0; j < 15; ++j) xw[j] = xrow[rb + j];
        u64 xwp[14];
        #pragma unroll
        for (int a = 0; a < 14; ++a) xwp[a] = pk2(xw[a], xw[a + 1]);
        #pragma unroll
        for (int i = 0; i < 8; ++i) {
            float kv = krow[l0 + i];
            u64 k2 = pk2(kv, kv);
            accp[0] = fma2(k2, xwp[7 - i], accp[0]);
            accp[1] = fma2(k2, xwp[9 - i], accp[1]);
            accp[2] = fma2(k2, xwp[11 - i], accp[2]);
            accp[3] = fma2(k2, xwp[13 - i], accp[3]);
        }
    }

    const float Dh = Dv[h0 + hh];
    float acc[8];
    #pragma unroll
    for (int p = 0; p < 4; ++p) {
        float2 f = upk2(accp[p]);
        acc[2 * p] = f.x; acc[2 * p + 1] = f.y;
    }
    #pragma unroll
    for (int j = 0; j < 8; ++j) {
        float xv = xrow[63 + t0 + j];
        float yv = fmaf(Dh, xv, acc[j]);
        float g = 0.5f * yv * (1.0f + erff(yv * 0.70710678118654752f));
        out[((size_t)b * L + c * T + t0 + j) * Hd + h0 + hh] = g;
    }
}

// ---------------------------------------------------------------------------
// Launch
// ---------------------------------------------------------------------------
extern "C" void kernel_launch(void* const* d_in, const int* in_sizes, int n_in,
                              void* d_out, int out_size) {
    const float* x      = (const float*)d_in[0];
    const float* log_dt = (const float*)d_in[1];
    const float* arl    = (const float*)d_in[2];
    const float* aim    = (const float*)d_in[3];
    const float* Bre    = (const float*)d_in[4];
    const float* Bim    = (const float*)d_in[5];
    const float* Cre    = (const float*)d_in[6];
    const float* Cim    = (const float*)d_in[7];
    const float* Dv     = (const float*)d_in[8];
    float* out = (float*)d_out;

    const long long ysElems = (long long)B * L * Hd;   // 16,777,216
    const long long stN     = (long long)B * Hd * N2;  // 131,072
    int stateMode = 0;
    if ((long long)out_size >= ysElems + 2 * stN) stateMode = 2;
    else if ((long long)out_size >= ysElems + stN) stateMode = 1;

    const int locSmem  = (T * Q + T * XRP) * 4;          // 50,176 B
    const int corrSmem = (Q * CBP + Q * T) * 4;          // 148,480 B
    static int attrDone = 0;
    if (!attrDone) {
        cudaFuncSetAttribute(k_loc, cudaFuncAttributeMaxDynamicSharedMemorySize, locSmem);
        cudaFuncSetAttribute(k_corrf, cudaFuncAttributeMaxDynamicSharedMemorySize, corrSmem);
        attrDone = 1;
    }

    k_prep<<<(HN + 255) / 256, 256>>>(log_dt, arl, aim, Bre, Bim, Cre, Cim);
    k_K<<<(Hd * T + 255) / 256, 256>>>();
    k_wtr<<<Hd, 256>>>();
    k_tr<<<dim3(BL / 64, Hd / 64), 256>>>(x);
    k_loc<<<dim3(Hd, CB / 128), 256, locSmem>>>();
    k_corrf<<<Hd, 256, corrSmem>>>(out, stateMode);
    k_out<<<dim3(CB, Hd / 32), 256>>>(x, Dv, out);
}

// round 11
// speedup vs baseline: 1.6151x; 1.6151x over previous
#include <cuda_runtime.h>
#include <math.h>

// Problem constants
#define Hd 512
#define L 4096
#define B 8
#define N2 32
#define HN (Hd * N2)
#define T 64            // chunk length
#define NCH (L / T)     // 64 chunks per sequence
#define CB (NCH * B)    // 512 chunk-rows
#define Q 64            // 2*N2 (re block + im block)
#define BL (B * L)      // 32768
#define CBP 516         // padded locS row stride (floats)
#define XRP 132         // padded xrs row stride
#define STP 66          // stg row stride

typedef unsigned long long u64;

__device__ __forceinline__ u64 pk2(float lo, float hi) {
    u64 r; asm("mov.b64 %0, {%1, %2};" : "=l"(r) : "f"(lo), "f"(hi)); return r;
}
__device__ __forceinline__ float2 upk2(u64 v) {
    float2 f; asm("mov.b64 {%0, %1}, %2;" : "=f"(f.x), "=f"(f.y) : "l"(v)); return f;
}
__device__ __forceinline__ u64 fma2(u64 a, u64 b, u64 c) {
    u64 d; asm("fma.rn.f32x2 %0, %1, %2, %3;" : "=l"(d) : "l"(a), "l"(b), "l"(c)); return d;
}

// ---------------------------------------------------------------------------
// Device-global parameter / scratch arrays
// ---------------------------------------------------------------------------
__device__ float g_C2re[HN], g_C2imN[HN];
__device__ float g_dATre[HN], g_dATim[HN];                  // dA^T (double-derived)
__device__ __align__(16) float g_E[Hd * T * Q];             // [h][tau][q]: dA^{T-1-tau} dB
__device__ __align__(16) float g_Wt[Hd * T * Q];            // [h][t][q] (prep output)
__device__ __align__(16) float g_W[Hd * Q * T];             // [h][q][t] (transposed)
__device__ float g_K[Hd * T];                               // conv kernel
__device__ __align__(16) float g_xT[(size_t)Hd * BL];       // transposed x: [h][b*L+t]
__device__ __align__(16) float g_loc[(size_t)Hd * Q * CB];  // [h][q][cb]
__device__ __align__(16) float g_corr[(size_t)Hd * CB * T]; // [h][cb][t]

// ---------------------------------------------------------------------------
// K0: per-(h,n) discretization + E/Wt tables
// ---------------------------------------------------------------------------
__global__ void k_prep(const float* __restrict__ log_dt,
                       const float* __restrict__ arl,
                       const float* __restrict__ aim,
                       const float* __restrict__ Bre,
                       const float* __restrict__ Bim,
                       const float* __restrict__ Cre,
                       const float* __restrict__ Cim) {
    int i = blockIdx.x * blockDim.x + threadIdx.x;
    if (i >= HN) return;
    int h = i >> 5, n = i & 31;
    float dt   = expf(log_dt[h]);
    float are  = -expf(arl[i]);
    float aimv = aim[i];
    float zre = are * dt, zim = aimv * dt;
    float sz, cz; sincosf(zim, &sz, &cz);
    float ez = expf(zre);
    float dre = ez * cz, dimv = ez * sz;   // dA
    float sh = sinf(0.5f * zim);
    float em1re = expm1f(zre) * cz - 2.0f * sh * sh;
    float em1im = ez * sz;
    float inv = 1.0f / (are * are + aimv * aimv);
    float fre = (em1re * are + em1im * aimv) * inv;
    float fim = (em1im * are - em1re * aimv) * inv;
    float bre0 = Bre[i], bim0 = Bim[i];
    float dbre = bre0 * fre - bim0 * fim;
    float dbim = bre0 * fim + bim0 * fre;
    g_C2re[i]  =  2.0f * Cre[i];
    g_C2imN[i] = -2.0f * Cim[i];
    double zred = (double)are * (double)dt * (double)T;
    double zimd = (double)aimv * (double)dt * (double)T;
    double ezd = exp(zred);
    g_dATre[i] = (float)(ezd * cos(zimd));
    g_dATim[i] = (float)(ezd * sin(zimd));
    // E[tau] = dA^{T-1-tau} dB (reversed rows) ; Wt[t][q] = C dA^{t+1}
    float pre = dbre, pim = dbim;
    float cre0 = Cre[i], cim0 = Cim[i];
    float wre = cre0 * dre - cim0 * dimv;
    float wim = cre0 * dimv + cim0 * dre;
    for (int l = 0; l < T; ++l) {
        g_E[((size_t)h * T + (T - 1 - l)) * Q + n]      = pre;
        g_E[((size_t)h * T + (T - 1 - l)) * Q + 32 + n] = pim;
        g_Wt[((size_t)h * T + l) * Q + n]      =  2.0f * wre;
        g_Wt[((size_t)h * T + l) * Q + 32 + n] = -2.0f * wim;
        float tre = pre * dre - pim * dimv; pim = pre * dimv + pim * dre; pre = tre;
        float ure = wre * dre - wim * dimv; wim = wre * dimv + wim * dre; wre = ure;
    }
}

// K0b: conv kernel K[h][l]
__global__ void k_K() {
    int i = blockIdx.x * blockDim.x + threadIdx.x;
    if (i >= Hd * T) return;
    int h = i >> 6, l = i & 63;
    const float* e   = &g_E[((size_t)h * T + (T - 1 - l)) * Q];
    const float* c2r = &g_C2re[h * 32];
    const float* c2i = &g_C2imN[h * 32];
    float s = 0.0f;
    #pragma unroll 8
    for (int n = 0; n < 32; ++n)
        s = fmaf(c2r[n], e[n], fmaf(c2i[n], e[32 + n], s));
    g_K[i] = s;
}

// K0c: per-h transpose Wt[t][q] -> W[q][t]
__global__ void __launch_bounds__(256) k_wtr() {
    __shared__ float wt[T * 68];
    const int h = blockIdx.x, tid = threadIdx.x;
    for (int k = tid; k < T * Q / 4; k += 256) {
        int t = k >> 4, qq = (k & 15) * 4;
        *reinterpret_cast<float4*>(&wt[t * 68 + qq]) =
            reinterpret_cast<const float4*>(g_Wt + (size_t)h * T * Q)[k];
    }
    __syncthreads();
    for (int k = tid; k < Q * T / 4; k += 256) {
        int q = k >> 4, tq = (k & 15) * 4;
        float4 v = make_float4(wt[(tq + 0) * 68 + q], wt[(tq + 1) * 68 + q],
                               wt[(tq + 2) * 68 + q], wt[(tq + 3) * 68 + q]);
        *reinterpret_cast<float4*>(&g_W[((size_t)h * Q + q) * T + tq]) = v;
    }
}

// ---------------------------------------------------------------------------
// K-tr: transpose x [bt][h] -> xT [h][bt], 64x64 tiles, float4 global I/O
// ---------------------------------------------------------------------------
__global__ void __launch_bounds__(256) k_tr(const float* __restrict__ x) {
    __shared__ float tile[64 * 65];
    const int bt0 = blockIdx.x * 64;
    const int h0  = blockIdx.y * 64;
    const int tid = threadIdx.x;
    #pragma unroll
    for (int it = 0; it < 4; ++it) {
        int idx = tid + it * 256;           // [0,1024)
        int r = idx >> 4, q = idx & 15;
        float4 v = *reinterpret_cast<const float4*>(
            &x[(size_t)(bt0 + r) * Hd + h0 + q * 4]);
        float* tr = &tile[r * 65 + q * 4];
        tr[0] = v.x; tr[1] = v.y; tr[2] = v.z; tr[3] = v.w;
    }
    __syncthreads();
    #pragma unroll
    for (int it = 0; it < 4; ++it) {
        int idx = tid + it * 256;
        int hh = idx >> 4, rq = idx & 15;
        float4 v = make_float4(tile[(rq * 4 + 0) * 65 + hh],
                               tile[(rq * 4 + 1) * 65 + hh],
                               tile[(rq * 4 + 2) * 65 + hh],
                               tile[(rq * 4 + 3) * 65 + hh]);
        *reinterpret_cast<float4*>(&g_xT[(size_t)(h0 + hh) * BL + bt0 + rq * 4]) = v;
    }
}

// ---------------------------------------------------------------------------
// K1: loc[h][q][cb] = sum_tau E[h][tau][q] * x[cb][tau]
// 4 cb per lane, f32x2. grid (Hd, CB/128), block 256, dynamic smem.
// ---------------------------------------------------------------------------
__global__ void __launch_bounds__(256) k_loc() {
    extern __shared__ float sm[];
    float* Es  = sm;                // [64][64] 16KB
    float* xrs = sm + T * Q;        // [64][XRP] 33.8KB
    const int h = blockIdx.x;
    const int cb0 = blockIdx.y * 128;
    const int tid = threadIdx.x;
    for (int k = tid; k < T * Q / 4; k += 256)
        reinterpret_cast<float4*>(Es)[k] =
            reinterpret_cast<const float4*>(g_E + (size_t)h * T * Q)[k];
    for (int k = tid; k < 128 * T; k += 256) {
        int c2 = k >> 6, tau = k & 63;
        int cb = cb0 + c2, b = cb & 7, c = cb >> 3;
        xrs[tau * XRP + c2] = g_xT[(size_t)h * BL + b * L + c * T + tau];
    }
    __syncthreads();
    const int cc = tid & 31, w = tid >> 5, q0 = w * 8;
    u64 acc[4][4];
    #pragma unroll
    for (int a = 0; a < 4; ++a)
        #pragma unroll
        for (int p = 0; p < 4; ++p) acc[a][p] = 0ull;
    #pragma unroll 4
    for (int tau = 0; tau < T; ++tau) {
        float4 xv = *reinterpret_cast<const float4*>(&xrs[tau * XRP + cc * 4]);
        ulonglong2 ea = *reinterpret_cast<const ulonglong2*>(&Es[tau * Q + q0]);
        ulonglong2 eb = *reinterpret_cast<const ulonglong2*>(&Es[tau * Q + q0 + 4]);
        u64 xx;
        xx = pk2(xv.x, xv.x);
        acc[0][0] = fma2(ea.x, xx, acc[0][0]); acc[0][1] = fma2(ea.y, xx, acc[0][1]);
        acc[0][2] = fma2(eb.x, xx, acc[0][2]); acc[0][3] = fma2(eb.y, xx, acc[0][3]);
        xx = pk2(xv.y, xv.y);
        acc[1][0] = fma2(ea.x, xx, acc[1][0]); acc[1][1] = fma2(ea.y, xx, acc[1][1]);
        acc[1][2] = fma2(eb.x, xx, acc[1][2]); acc[1][3] = fma2(eb.y, xx, acc[1][3]);
        xx = pk2(xv.z, xv.z);
        acc[2][0] = fma2(ea.x, xx, acc[2][0]); acc[2][1] = fma2(ea.y, xx, acc[2][1]);
        acc[2][2] = fma2(eb.x, xx, acc[2][2]); acc[2][3] = fma2(eb.y, xx, acc[2][3]);
        xx = pk2(xv.w, xv.w);
        acc[3][0] = fma2(ea.x, xx, acc[3][0]); acc[3][1] = fma2(ea.y, xx, acc[3][1]);
        acc[3][2] = fma2(eb.x, xx, acc[3][2]); acc[3][3] = fma2(eb.y, xx, acc[3][3]);
    }
    #pragma unroll
    for (int p = 0; p < 4; ++p) {
        float2 f0 = upk2(acc[0][p]), f1 = upk2(acc[1][p]);
        float2 f2 = upk2(acc[2][p]), f3 = upk2(acc[3][p]);
        int q = q0 + 2 * p;
        *reinterpret_cast<float4*>(&g_loc[((size_t)h * Q + q) * CB + cb0 + cc * 4]) =
            make_float4(f0.x, f1.x, f2.x, f3.x);
        *reinterpret_cast<float4*>(&g_loc[((size_t)h * Q + q + 1) * CB + cb0 + cc * 4]) =
            make_float4(f0.y, f1.y, f2.y, f3.y);
    }
}

// ---------------------------------------------------------------------------
// K2: fused carry-scan + correction GEMM. One block per h. (R9 version)
// smem: locS [Q][CBP] + Ws [Q][T] + stg [128][STP]
// ---------------------------------------------------------------------------
__global__ void __launch_bounds__(256) k_corrf(float* __restrict__ out, int stateMode) {
    extern __shared__ float sm[];
    float* locS = sm;                    // 64*516 = 132KB
    float* Ws   = sm + Q * CBP;          // 16KB
    float* stg  = Ws + Q * T;            // 128*66 = 33.8KB
    const int h = blockIdx.x;
    const int tid = threadIdx.x;
    for (int k = tid; k < Q * T / 4; k += 256)
        reinterpret_cast<float4*>(Ws)[k] =
            reinterpret_cast<const float4*>(g_W + (size_t)h * Q * T)[k];
    for (int k = tid; k < Q * CB / 4; k += 256) {
        int q = k >> 7, c4 = k & 127;
        *reinterpret_cast<float4*>(&locS[q * CBP + c4 * 4]) =
            reinterpret_cast<const float4*>(g_loc + (size_t)h * Q * CB)[k];
    }
    __syncthreads();
    // exclusive carry scan along chunks, in place; thread = (n, b)
    {
        int n = tid >> 3, b = tid & 7;
        float aRe = g_dATre[h * 32 + n], aIm = g_dATim[h * 32 + n];
        float* pr = &locS[n * CBP + b];
        float* pi = &locS[(32 + n) * CBP + b];
        float cre = 0.0f, cim = 0.0f;
        #pragma unroll 4
        for (int c = 0; c < NCH; ++c) {
            float lre = pr[c * 8], lim = pi[c * 8];
            pr[c * 8] = cre; pi[c * 8] = cim;
            float nre = fmaf(aRe, cre, fmaf(-aIm, cim, lre));
            float nim = fmaf(aIm, cre, fmaf(aRe, cim, lim));
            cre = nre; cim = nim;
        }
        if (stateMode > 0) {
            size_t ysEnd = (size_t)B * L * Hd;
            size_t idx = ((size_t)b * Hd + h) * N2 + n;
            out[ysEnd + idx] = cre;
            if (stateMode > 1) out[ysEnd + (size_t)B * Hd * N2 + idx] = cim;
        }
    }
    __syncthreads();
    // correction GEMM: corr[cb][t] = sum_q W[q][t] * s0[q][cb]
    const int cc = tid & 31, w = tid >> 5, t0 = w * 8;
    for (int pass = 0; pass < 4; ++pass) {
        const int cbl0 = pass * 128;
        u64 acc[4][4];
        #pragma unroll
        for (int a = 0; a < 4; ++a)
            #pragma unroll
            for (int p = 0; p < 4; ++p) acc[a][p] = 0ull;
        #pragma unroll 4
        for (int q = 0; q < Q; ++q) {
            float4 sv = *reinterpret_cast<const float4*>(&locS[q * CBP + cbl0 + cc * 4]);
            ulonglong2 wa = *reinterpret_cast<const ulonglong2*>(&Ws[q * T + t0]);
            ulonglong2 wb = *reinterpret_cast<const ulonglong2*>(&Ws[q * T + t0 + 4]);
            u64 xx;
            xx = pk2(sv.x, sv.x);
            acc[0][0] = fma2(wa.x, xx, acc[0][0]); acc[0][1] = fma2(wa.y, xx, acc[0][1]);
            acc[0][2] = fma2(wb.x, xx, acc[0][2]); acc[0][3] = fma2(wb.y, xx, acc[0][3]);
            xx = pk2(sv.y, sv.y);
            acc[1][0] = fma2(wa.x, xx, acc[1][0]); acc[1][1] = fma2(wa.y, xx, acc[1][1]);
            acc[1][2] = fma2(wb.x, xx, acc[1][2]); acc[1][3] = fma2(wb.y, xx, acc[1][3]);
            xx = pk2(sv.z, sv.z);
            acc[2][0] = fma2(wa.x, xx, acc[2][0]); acc[2][1] = fma2(wa.y, xx, acc[2][1]);
            acc[2][2] = fma2(wb.x, xx, acc[2][2]); acc[2][3] = fma2(wb.y, xx, acc[2][3]);
            xx = pk2(sv.w, sv.w);
            acc[3][0] = fma2(wa.x, xx, acc[3][0]); acc[3][1] = fma2(wa.y, xx, acc[3][1]);
            acc[3][2] = fma2(wb.x, xx, acc[3][2]); acc[3][3] = fma2(wb.y, xx, acc[3][3]);
        }
        #pragma unroll
        for (int a = 0; a < 4; ++a) {
            float* row = &stg[(cc * 4 + a) * STP + t0];
            #pragma unroll
            for (int p = 0; p < 4; ++p) {
                float2 f = upk2(acc[a][p]);
                *reinterpret_cast<float2*>(&row[2 * p]) = f;
            }
        }
        __syncthreads();
        for (int k = tid; k < 128 * T / 4; k += 256) {
            int r = k >> 4, tp = (k & 15) * 4;
            float2 a = *reinterpret_cast<const float2*>(&stg[r * STP + tp]);
            float2 b2 = *reinterpret_cast<const float2*>(&stg[r * STP + tp + 2]);
            *reinterpret_cast<float4*>(&g_corr[((size_t)h * CB + cbl0 + r) * T + tp]) =
                make_float4(a.x, a.y, b2.x, b2.y);
        }
        __syncthreads();
    }
}

// ---------------------------------------------------------------------------
// K4: output = causal conv(K,x) + corr + D*x, then exact GELU.
// f32x2-packed conv. grid (CB, Hd/32), block 256
// ---------------------------------------------------------------------------
__global__ void __launch_bounds__(256) k_out(const float* __restrict__ x,
                                             const float* __restrict__ Dv,
                                             float* __restrict__ out) {
    __shared__ float xs[32 * 133];
    __shared__ float Ks[32 * 65];
    __shared__ float cs[32 * 65];
    const int cb = blockIdx.x, h0 = blockIdx.y * 32;
    const int b = cb & 7, c = cb >> 3;
    const int tid = threadIdx.x;
    for (int k = tid; k < 32 * 63; k += 256) {
        int hh = k & 31, r = k >> 5;
        xs[hh * 133 + r] = 0.0f;
    }
    for (int k = tid; k < 32 * 64; k += 256) {
        int hh = k & 31, tt = k >> 5;
        xs[hh * 133 + 63 + tt] = x[((size_t)b * L + c * T + tt) * Hd + h0 + hh];
    }
    for (int k = tid; k < 32 * 64; k += 256) {
        int hh = k & 31, l = k >> 5;
        Ks[hh * 65 + l] = g_K[(h0 + hh) * T + l];
    }
    for (int k = tid; k < 2048; k += 256) {
        int hh = k >> 6, tt = k & 63;
        cs[hh * 65 + tt] = g_corr[((size_t)(h0 + hh) * CB + cb) * T + tt];
    }
    __syncthreads();

    const int hh = tid & 31, w = tid >> 5, t0 = w * 8;
    u64 accp[4];
    #pragma unroll
    for (int p = 0; p < 4; ++p)
        accp[p] = pk2(cs[hh * 65 + t0 + 2 * p], cs[hh * 65 + t0 + 2 * p + 1]);

    const float* xrow = &xs[hh * 133];
    const float* krow = &Ks[hh * 65];
    for (int lt = 0; lt <= w; ++lt) {
        const int l0 = lt * 8;
        const int rb = 63 + t0 - l0 - 7;
        float xw[15];
        #pragma unroll
        for (int j = 0; j < 15; ++j) xw[j] = xrow[rb + j];
        u64 xwp[14];
        #pragma unroll
        for (int a = 0; a < 14; ++a) xwp[a] = pk2(xw[a], xw[a + 1]);
        #pragma unroll
        for (int i = 0; i < 8; ++i) {
            float kv = krow[l0 + i];
            u64 k2 = pk2(kv, kv);
            accp[0] = fma2(k2, xwp[7 - i], accp[0]);
            accp[1] = fma2(k2, xwp[9 - i], accp[1]);
            accp[2] = fma2(k2, xwp[11 - i], accp[2]);
            accp[3] = fma2(k2, xwp[13 - i], accp[3]);
        }
    }

    const float Dh = Dv[h0 + hh];
    float acc[8];
    #pragma unroll
    for (int p = 0; p < 4; ++p) {
        float2 f = upk2(accp[p]);
        acc[2 * p] = f.x; acc[2 * p + 1] = f.y;
    }
    #pragma unroll
    for (int j = 0; j < 8; ++j) {
        float xv = xrow[63 + t0 + j];
        float yv = fmaf(Dh, xv, acc[j]);
        float g = 0.5f * yv * (1.0f + erff(yv * 0.70710678118654752f));
        out[((size_t)b * L + c * T + t0 + j) * Hd + h0 + hh] = g;
    }
}

// ---------------------------------------------------------------------------
// Launch
// ---------------------------------------------------------------------------
extern "C" void kernel_launch(void* const* d_in, const int* in_sizes, int n_in,
                              void* d_out, int out_size) {
    const float* x      = (const float*)d_in[0];
    const float* log_dt = (const float*)d_in[1];
    const float* arl    = (const float*)d_in[2];
    const float* aim    = (const float*)d_in[3];
    const float* Bre    = (const float*)d_in[4];
    const float* Bim    = (const float*)d_in[5];
    const float* Cre    = (const float*)d_in[6];
    const float* Cim    = (const float*)d_in[7];
    const float* Dv     = (const float*)d_in[8];
    float* out = (float*)d_out;

    const long long ysElems = (long long)B * L * Hd;   // 16,777,216
    const long long stN     = (long long)B * Hd * N2;  // 131,072
    int stateMode = 0;
    if ((long long)out_size >= ysElems + 2 * stN) stateMode = 2;
    else if ((long long)out_size >= ysElems + stN) stateMode = 1;

    const int locSmem  = (T * Q + T * XRP) * 4;                 // 50,176 B
    const int corrSmem = (Q * CBP + Q * T + 128 * STP) * 4;     // 182,272 B
    static int attrDone = 0;
    if (!attrDone) {
        cudaFuncSetAttribute(k_loc, cudaFuncAttributeMaxDynamicSharedMemorySize, locSmem);
        cudaFuncSetAttribute(k_corrf, cudaFuncAttributeMaxDynamicSharedMemorySize, corrSmem);
        attrDone = 1;
    }

    k_prep<<<(HN + 255) / 256, 256>>>(log_dt, arl, aim, Bre, Bim, Cre, Cim);
    k_K<<<(Hd * T + 255) / 256, 256>>>();
    k_wtr<<<Hd, 256>>>();
    k_tr<<<dim3(BL / 64, Hd / 64), 256>>>(x);
    k_loc<<<dim3(Hd, CB / 128), 256, locSmem>>>();
    k_corrf<<<Hd, 256, corrSmem>>>(out, stateMode);
    k_out<<<dim3(CB, Hd / 32), 256>>>(x, Dv, out);
}

// round 12
// speedup vs baseline: 2.1275x; 1.3173x over previous
#include <cuda_runtime.h>
#include <math.h>

// Problem constants
#define Hd 512
#define L 4096
#define B 8
#define N2 32
#define HN (Hd * N2)
#define T 64            // chunk length
#define NCH (L / T)     // 64 chunks per sequence
#define CB (NCH * B)    // 512 chunk-rows
#define Q 64            // 2*N2 (re block + im block)
#define BL (B * L)      // 32768
#define HALF (CB / 2)   // 256 cb per corr block
#define CBPH 260        // padded locS row stride (floats)
#define XRP 132         // padded xrs row stride
#define STP 66          // stg row stride
#define NCC 4           // chunks per k_out block

typedef unsigned long long u64;

__device__ __forceinline__ u64 pk2(float lo, float hi) {
    u64 r; asm("mov.b64 %0, {%1, %2};" : "=l"(r) : "f"(lo), "f"(hi)); return r;
}
__device__ __forceinline__ float2 upk2(u64 v) {
    float2 f; asm("mov.b64 {%0, %1}, %2;" : "=f"(f.x), "=f"(f.y) : "l"(v)); return f;
}
__device__ __forceinline__ u64 fma2(u64 a, u64 b, u64 c) {
    u64 d; asm("fma.rn.f32x2 %0, %1, %2, %3;" : "=l"(d) : "l"(a), "l"(b), "l"(c)); return d;
}

// ---------------------------------------------------------------------------
// Device-global parameter / scratch arrays
// ---------------------------------------------------------------------------
__device__ float g_dATre[HN], g_dATim[HN];                  // dA^T (double-derived)
__device__ __align__(16) float g_E[Hd * T * Q];             // [h][tau][q]: dA^{T-1-tau} dB
__device__ __align__(16) float g_W[Hd * Q * T];             // [h][q][t]
__device__ float g_K[Hd * T];                               // conv kernel
__device__ __align__(16) float g_xT[(size_t)Hd * BL];       // transposed x: [h][b*L+t]
__device__ __align__(16) float g_loc[(size_t)Hd * Q * CB];  // [h][q][cb]
__device__ __align__(16) float g_corr[(size_t)Hd * CB * T]; // [h][cb][t]

// ---------------------------------------------------------------------------
// K0 (fused): per-h discretization, E table, W table (+transpose), K kernel.
// grid Hd, block 32 (one warp; lane = mode n).
// ---------------------------------------------------------------------------
__global__ void __launch_bounds__(32) k_prep(const float* __restrict__ log_dt,
                                             const float* __restrict__ arl,
                                             const float* __restrict__ aim,
                                             const float* __restrict__ Bre,
                                             const float* __restrict__ Bim,
                                             const float* __restrict__ Cre,
                                             const float* __restrict__ Cim) {
    __shared__ float wt[T * 68];   // [t][q]
    const int h = blockIdx.x;
    const int n = threadIdx.x;
    const int i = h * 32 + n;
    float dt   = expf(log_dt[h]);
    float are  = -expf(arl[i]);
    float aimv = aim[i];
    float zre = are * dt, zim = aimv * dt;
    float sz, cz; sincosf(zim, &sz, &cz);
    float ez = expf(zre);
    float dre = ez * cz, dimv = ez * sz;   // dA
    float sh = sinf(0.5f * zim);
    float em1re = expm1f(zre) * cz - 2.0f * sh * sh;
    float em1im = ez * sz;
    float inv = 1.0f / (are * are + aimv * aimv);
    float fre = (em1re * are + em1im * aimv) * inv;
    float fim = (em1im * are - em1re * aimv) * inv;
    float bre0 = Bre[i], bim0 = Bim[i];
    float dbre = bre0 * fre - bim0 * fim;
    float dbim = bre0 * fim + bim0 * fre;
    float c2re  =  2.0f * Cre[i];
    float c2imN = -2.0f * Cim[i];
    double zred = (double)are * (double)dt * (double)T;
    double zimd = (double)aimv * (double)dt * (double)T;
    double ezd = exp(zred);
    g_dATre[i] = (float)(ezd * cos(zimd));
    g_dATim[i] = (float)(ezd * sin(zimd));
    // E[tau] = dA^{T-1-tau} dB (reversed rows); W[t] = C dA^{t+1}; K[l]
    float pre = dbre, pim = dbim;
    float cre0 = Cre[i], cim0 = Cim[i];
    float wre = cre0 * dre - cim0 * dimv;
    float wim = cre0 * dimv + cim0 * dre;
    for (int l = 0; l < T; ++l) {
        g_E[((size_t)h * T + (T - 1 - l)) * Q + n]      = pre;
        g_E[((size_t)h * T + (T - 1 - l)) * Q + 32 + n] = pim;
        wt[l * 68 + n]      =  2.0f * wre;
        wt[l * 68 + 32 + n] = -2.0f * wim;
        // K[l] = sum_n (2Cre*pre - 2Cim*pim)
        float kl = fmaf(c2re, pre, c2imN * pim);
        kl += __shfl_xor_sync(0xffffffffu, kl, 1);
        kl += __shfl_xor_sync(0xffffffffu, kl, 2);
        kl += __shfl_xor_sync(0xffffffffu, kl, 4);
        kl += __shfl_xor_sync(0xffffffffu, kl, 8);
        kl += __shfl_xor_sync(0xffffffffu, kl, 16);
        if (n == 0) g_K[h * T + l] = kl;
        float tre = pre * dre - pim * dimv; pim = pre * dimv + pim * dre; pre = tre;
        float ure = wre * dre - wim * dimv; wim = wre * dimv + wim * dre; wre = ure;
    }
    __syncthreads();
    // transpose wt [t][q] -> g_W [q][t] (float4 stores)
    for (int k = n; k < Q * T / 4; k += 32) {
        int q = k >> 4, tq = (k & 15) * 4;
        float4 v = make_float4(wt[(tq + 0) * 68 + q], wt[(tq + 1) * 68 + q],
                               wt[(tq + 2) * 68 + q], wt[(tq + 3) * 68 + q]);
        *reinterpret_cast<float4*>(&g_W[((size_t)h * Q + q) * T + tq]) = v;
    }
}

// ---------------------------------------------------------------------------
// K-tr: transpose x [bt][h] -> xT [h][bt], 64x64 tiles, float4 global I/O
// ---------------------------------------------------------------------------
__global__ void __launch_bounds__(256) k_tr(const float* __restrict__ x) {
    __shared__ float tile[64 * 65];
    const int bt0 = blockIdx.x * 64;
    const int h0  = blockIdx.y * 64;
    const int tid = threadIdx.x;
    #pragma unroll
    for (int it = 0; it < 4; ++it) {
        int idx = tid + it * 256;           // [0,1024)
        int r = idx >> 4, q = idx & 15;
        float4 v = *reinterpret_cast<const float4*>(
            &x[(size_t)(bt0 + r) * Hd + h0 + q * 4]);
        float* tr = &tile[r * 65 + q * 4];
        tr[0] = v.x; tr[1] = v.y; tr[2] = v.z; tr[3] = v.w;
    }
    __syncthreads();
    #pragma unroll
    for (int it = 0; it < 4; ++it) {
        int idx = tid + it * 256;
        int hh = idx >> 4, rq = idx & 15;
        float4 v = make_float4(tile[(rq * 4 + 0) * 65 + hh],
                               tile[(rq * 4 + 1) * 65 + hh],
                               tile[(rq * 4 + 2) * 65 + hh],
                               tile[(rq * 4 + 3) * 65 + hh]);
        *reinterpret_cast<float4*>(&g_xT[(size_t)(h0 + hh) * BL + bt0 + rq * 4]) = v;
    }
}

// ---------------------------------------------------------------------------
// K1: loc[h][q][cb] = sum_tau E[h][tau][q] * x[cb][tau]
// 4 cb per lane, f32x2. grid (Hd, CB/128), block 256, dynamic smem.
// ---------------------------------------------------------------------------
__global__ void __launch_bounds__(256) k_loc() {
    extern __shared__ float sm[];
    float* Es  = sm;                // [64][64] 16KB
    float* xrs = sm + T * Q;        // [64][XRP] 33.8KB
    const int h = blockIdx.x;
    const int cb0 = blockIdx.y * 128;
    const int tid = threadIdx.x;
    for (int k = tid; k < T * Q / 4; k += 256)
        reinterpret_cast<float4*>(Es)[k] =
            reinterpret_cast<const float4*>(g_E + (size_t)h * T * Q)[k];
    for (int k = tid; k < 128 * T; k += 256) {
        int c2 = k >> 6, tau = k & 63;
        int cb = cb0 + c2, b = cb & 7, c = cb >> 3;
        xrs[tau * XRP + c2] = g_xT[(size_t)h * BL + b * L + c * T + tau];
    }
    __syncthreads();
    const int cc = tid & 31, w = tid >> 5, q0 = w * 8;
    u64 acc[4][4];
    #pragma unroll
    for (int a = 0; a < 4; ++a)
        #pragma unroll
        for (int p = 0; p < 4; ++p) acc[a][p] = 0ull;
    #pragma unroll 4
    for (int tau = 0; tau < T; ++tau) {
        float4 xv = *reinterpret_cast<const float4*>(&xrs[tau * XRP + cc * 4]);
        ulonglong2 ea = *reinterpret_cast<const ulonglong2*>(&Es[tau * Q + q0]);
        ulonglong2 eb = *reinterpret_cast<const ulonglong2*>(&Es[tau * Q + q0 + 4]);
        u64 xx;
        xx = pk2(xv.x, xv.x);
        acc[0][0] = fma2(ea.x, xx, acc[0][0]); acc[0][1] = fma2(ea.y, xx, acc[0][1]);
        acc[0][2] = fma2(eb.x, xx, acc[0][2]); acc[0][3] = fma2(eb.y, xx, acc[0][3]);
        xx = pk2(xv.y, xv.y);
        acc[1][0] = fma2(ea.x, xx, acc[1][0]); acc[1][1] = fma2(ea.y, xx, acc[1][1]);
        acc[1][2] = fma2(eb.x, xx, acc[1][2]); acc[1][3] = fma2(eb.y, xx, acc[1][3]);
        xx = pk2(xv.z, xv.z);
        acc[2][0] = fma2(ea.x, xx, acc[2][0]); acc[2][1] = fma2(ea.y, xx, acc[2][1]);
        acc[2][2] = fma2(eb.x, xx, acc[2][2]); acc[2][3] = fma2(eb.y, xx, acc[2][3]);
        xx = pk2(xv.w, xv.w);
        acc[3][0] = fma2(ea.x, xx, acc[3][0]); acc[3][1] = fma2(ea.y, xx, acc[3][1]);
        acc[3][2] = fma2(eb.x, xx, acc[3][2]); acc[3][3] = fma2(eb.y, xx, acc[3][3]);
    }
    #pragma unroll
    for (int p = 0; p < 4; ++p) {
        float2 f0 = upk2(acc[0][p]), f1 = upk2(acc[1][p]);
        float2 f2 = upk2(acc[2][p]), f3 = upk2(acc[3][p]);
        int q = q0 + 2 * p;
        *reinterpret_cast<float4*>(&g_loc[((size_t)h * Q + q) * CB + cb0 + cc * 4]) =
            make_float4(f0.x, f1.x, f2.x, f3.x);
        *reinterpret_cast<float4*>(&g_loc[((size_t)h * Q + q + 1) * CB + cb0 + cc * 4]) =
            make_float4(f0.y, f1.y, f2.y, f3.y);
    }
}

// ---------------------------------------------------------------------------
// K2: fused carry-scan + correction GEMM, split into cb-halves.
// grid (Hd, 2), block 256. smem: locS [Q][CBPH] + Ws [Q][T] + stg [64][STP].
// Half 1 recomputes its carry-in by streaming chunks 0..31 from global.
// ---------------------------------------------------------------------------
__global__ void __launch_bounds__(256) k_corrf(float* __restrict__ out, int stateMode) {
    extern __shared__ float sm[];
    float* locS = sm;                    // 64*260 = 66.6KB
    float* Ws   = sm + Q * CBPH;         // 16KB
    float* stg  = Ws + Q * T;            // 64*66 = 16.9KB
    const int h = blockIdx.x;
    const int half = blockIdx.y;
    const int cbh = half * HALF;
    const int tid = threadIdx.x;
    for (int k = tid; k < Q * T / 4; k += 256)
        reinterpret_cast<float4*>(Ws)[k] =
            reinterpret_cast<const float4*>(g_W + (size_t)h * Q * T)[k];
    for (int k = tid; k < Q * HALF / 4; k += 256) {
        int q = k >> 6, c4 = k & 63;
        *reinterpret_cast<float4*>(&locS[q * CBPH + c4 * 4]) =
            *reinterpret_cast<const float4*>(&g_loc[((size_t)h * Q + q) * CB + cbh + c4 * 4]);
    }
    __syncthreads();
    // exclusive carry scan along this half's chunks, in place; thread = (n, b)
    {
        int n = tid >> 3, b = tid & 7;
        float aRe = g_dATre[h * 32 + n], aIm = g_dATim[h * 32 + n];
        float cre = 0.0f, cim = 0.0f;
        if (half == 1) {
            // stream first-half locals from global to build carry-in
            const float* gr = &g_loc[((size_t)h * Q + n) * CB + b];
            const float* gi = &g_loc[((size_t)h * Q + 32 + n) * CB + b];
            #pragma unroll 8
            for (int c = 0; c < NCH / 2; ++c) {
                float lre = __ldg(gr + c * 8), lim = __ldg(gi + c * 8);
                float nre = fmaf(aRe, cre, fmaf(-aIm, cim, lre));
                float nim = fmaf(aIm, cre, fmaf(aRe, cim, lim));
                cre = nre; cim = nim;
            }
        }
        float* pr = &locS[n * CBPH + b];
        float* pi = &locS[(32 + n) * CBPH + b];
        #pragma unroll 4
        for (int c = 0; c < NCH / 2; ++c) {
            float lre = pr[c * 8], lim = pi[c * 8];
            pr[c * 8] = cre; pi[c * 8] = cim;
            float nre = fmaf(aRe, cre, fmaf(-aIm, cim, lre));
            float nim = fmaf(aIm, cre, fmaf(aRe, cim, lim));
            cre = nre; cim = nim;
        }
        if (half == 1 && stateMode > 0) {
            size_t ysEnd = (size_t)B * L * Hd;
            size_t idx = ((size_t)b * Hd + h) * N2 + n;
            out[ysEnd + idx] = cre;
            if (stateMode > 1) out[ysEnd + (size_t)B * Hd * N2 + idx] = cim;
        }
    }
    __syncthreads();
    // correction GEMM: corr[cb][t] = sum_q W[q][t] * s0[q][cb]
    const int cc = tid & 31, w = tid >> 5, t0 = w * 8;
    for (int pass = 0; pass < 2; ++pass) {
        const int cbl0 = pass * 128;
        u64 acc[4][4];
        #pragma unroll
        for (int a = 0; a < 4; ++a)
            #pragma unroll
            for (int p = 0; p < 4; ++p) acc[a][p] = 0ull;
        #pragma unroll 4
        for (int q = 0; q < Q; ++q) {
            float4 sv = *reinterpret_cast<const float4*>(&locS[q * CBPH + cbl0 + cc * 4]);
            ulonglong2 wa = *reinterpret_cast<const ulonglong2*>(&Ws[q * T + t0]);
            ulonglong2 wb = *reinterpret_cast<const ulonglong2*>(&Ws[q * T + t0 + 4]);
            u64 xx;
            xx = pk2(sv.x, sv.x);
            acc[0][0] = fma2(wa.x, xx, acc[0][0]); acc[0][1] = fma2(wa.y, xx, acc[0][1]);
            acc[0][2] = fma2(wb.x, xx, acc[0][2]); acc[0][3] = fma2(wb.y, xx, acc[0][3]);
            xx = pk2(sv.y, sv.y);
            acc[1][0] = fma2(wa.x, xx, acc[1][0]); acc[1][1] = fma2(wa.y, xx, acc[1][1]);
            acc[1][2] = fma2(wb.x, xx, acc[1][2]); acc[1][3] = fma2(wb.y, xx, acc[1][3]);
            xx = pk2(sv.z, sv.z);
            acc[2][0] = fma2(wa.x, xx, acc[2][0]); acc[2][1] = fma2(wa.y, xx, acc[2][1]);
            acc[2][2] = fma2(wb.x, xx, acc[2][2]); acc[2][3] = fma2(wb.y, xx, acc[2][3]);
            xx = pk2(sv.w, sv.w);
            acc[3][0] = fma2(wa.x, xx, acc[3][0]); acc[3][1] = fma2(wa.y, xx, acc[3][1]);
            acc[3][2] = fma2(wb.x, xx, acc[3][2]); acc[3][3] = fma2(wb.y, xx, acc[3][3]);
        }
        // two store rounds through the 64-row staging buffer
        #pragma unroll
        for (int rnd = 0; rnd < 2; ++rnd) {
            if ((cc >> 4) == rnd) {
                #pragma unroll
                for (int a = 0; a < 4; ++a) {
                    float* row = &stg[(cc * 4 + a - rnd * 64) * STP + t0];
                    #pragma unroll
                    for (int p = 0; p < 4; ++p) {
                        float2 f = upk2(acc[a][p]);
                        *reinterpret_cast<float2*>(&row[2 * p]) = f;
                    }
                }
            }
            __syncthreads();
            for (int k = tid; k < 64 * T / 4; k += 256) {
                int r = k >> 4, tp = (k & 15) * 4;
                float2 a2 = *reinterpret_cast<const float2*>(&stg[r * STP + tp]);
                float2 b2 = *reinterpret_cast<const float2*>(&stg[r * STP + tp + 2]);
                *reinterpret_cast<float4*>(
                    &g_corr[((size_t)h * CB + cbh + cbl0 + rnd * 64 + r) * T + tp]) =
                    make_float4(a2.x, a2.y, b2.x, b2.y);
            }
            __syncthreads();
        }
    }
}

// ---------------------------------------------------------------------------
// K4: output = causal conv(K,x) + corr + D*x, then exact GELU.
// NCC chunks per block. grid (CB/NCC, Hd/32), block 256
// ---------------------------------------------------------------------------
__global__ void __launch_bounds__(256) k_out(const float* __restrict__ x,
                                             const float* __restrict__ Dv,
                                             float* __restrict__ out) {
    __shared__ float xs[32 * 133];
    __shared__ float Ks[32 * 65];
    __shared__ float cs[32 * 65];
    const int h0 = blockIdx.y * 32;
    const int tid = threadIdx.x;
    const int hh = tid & 31, w = tid >> 5, t0 = w * 8;
    // one-time: zero pad + K table
    for (int k = tid; k < 32 * 63; k += 256) {
        int h2 = k & 31, r = k >> 5;
        xs[h2 * 133 + r] = 0.0f;
    }
    for (int k = tid; k < 32 * 64; k += 256) {
        int h2 = k & 31, l = k >> 5;
        Ks[h2 * 65 + l] = g_K[(h0 + h2) * T + l];
    }
    const float Dh = Dv[h0 + hh];
    const float* xrow = &xs[hh * 133];
    const float* krow = &Ks[hh * 65];

    for (int ci = 0; ci < NCC; ++ci) {
        const int cb = blockIdx.x * NCC + ci;
        const int b = cb & 7, c = cb >> 3;
        __syncthreads();   // previous compute done before overwriting tiles
        for (int k = tid; k < 32 * 64; k += 256) {
            int h2 = k & 31, tt = k >> 5;
            xs[h2 * 133 + 63 + tt] = x[((size_t)b * L + c * T + tt) * Hd + h0 + h2];
        }
        for (int k = tid; k < 2048; k += 256) {
            int h2 = k >> 6, tt = k & 63;
            cs[h2 * 65 + tt] = g_corr[((size_t)(h0 + h2) * CB + cb) * T + tt];
        }
        __syncthreads();

        u64 accp[4];
        #pragma unroll
        for (int p = 0; p < 4; ++p)
            accp[p] = pk2(cs[hh * 65 + t0 + 2 * p], cs[hh * 65 + t0 + 2 * p + 1]);

        for (int lt = 0; lt <= w; ++lt) {
            const int l0 = lt * 8;
            const int rb = 63 + t0 - l0 - 7;
            float xw[15];
            #pragma unroll
            for (int j = 0; j < 15; ++j) xw[j] = xrow[rb + j];
            u64 xwp[14];
            #pragma unroll
            for (int a = 0; a < 14; ++a) xwp[a] = pk2(xw[a], xw[a + 1]);
            #pragma unroll
            for (int i = 0; i < 8; ++i) {
                float kv = krow[l0 + i];
                u64 k2 = pk2(kv, kv);
                accp[0] = fma2(k2, xwp[7 - i], accp[0]);
                accp[1] = fma2(k2, xwp[9 - i], accp[1]);
                accp[2] = fma2(k2, xwp[11 - i], accp[2]);
                accp[3] = fma2(k2, xwp[13 - i], accp[3]);
            }
        }

        float acc[8];
        #pragma unroll
        for (int p = 0; p < 4; ++p) {
            float2 f = upk2(accp[p]);
            acc[2 * p] = f.x; acc[2 * p + 1] = f.y;
        }
        #pragma unroll
        for (int j = 0; j < 8; ++j) {
            float xv = xrow[63 + t0 + j];
            float yv = fmaf(Dh, xv, acc[j]);
            float g = 0.5f * yv * (1.0f + erff(yv * 0.70710678118654752f));
            out[((size_t)b * L + c * T + t0 + j) * Hd + h0 + hh] = g;
        }
    }
}

// ---------------------------------------------------------------------------
// Launch
// ---------------------------------------------------------------------------
extern "C" void kernel_launch(void* const* d_in, const int* in_sizes, int n_in,
                              void* d_out, int out_size) {
    const float* x      = (const float*)d_in[0];
    const float* log_dt = (const float*)d_in[1];
    const float* arl    = (const float*)d_in[2];
    const float* aim    = (const float*)d_in[3];
    const float* Bre    = (const float*)d_in[4];
    const float* Bim    = (const float*)d_in[5];
    const float* Cre    = (const float*)d_in[6];
    const float* Cim    = (const float*)d_in[7];
    const float* Dv     = (const float*)d_in[8];
    float* out = (float*)d_out;

    const long long ysElems = (long long)B * L * Hd;   // 16,777,216
    const long long stN     = (long long)B * Hd * N2;  // 131,072
    int stateMode = 0;
    if ((long long)out_size >= ysElems + 2 * stN) stateMode = 2;
    else if ((long long)out_size >= ysElems + stN) stateMode = 1;

    const int locSmem  = (T * Q + T * XRP) * 4;                 // 50,176 B
    const int corrSmem = (Q * CBPH + Q * T + 64 * STP) * 4;     // 99,840 B
    static int attrDone = 0;
    if (!attrDone) {
        cudaFuncSetAttribute(k_loc, cudaFuncAttributeMaxDynamicSharedMemorySize, locSmem);
        cudaFuncSetAttribute(k_corrf, cudaFuncAttributeMaxDynamicSharedMemorySize, corrSmem);
        attrDone = 1;
    }

    k_prep<<<Hd, 32>>>(log_dt, arl, aim, Bre, Bim, Cre, Cim);
    k_tr<<<dim3(BL / 64, Hd / 64), 256>>>(x);
    k_loc<<<dim3(Hd, CB / 128), 256, locSmem>>>();
    k_corrf<<<dim3(Hd, 2), 256, corrSmem>>>(out, stateMode);
    k_out<<<dim3(CB / NCC, Hd / 32), 256>>>(x, Dv, out);
}

// round 13
// speedup vs baseline: 2.2551x; 1.0600x over previous
#include <cuda_runtime.h>
#include <math.h>

// Problem constants
#define Hd 512
#define L 4096
#define B 8
#define N2 32
#define HN (Hd * N2)
#define T 64            // chunk length
#define NCH (L / T)     // 64 chunks per sequence
#define CB (NCH * B)    // 512 chunk-rows
#define Q 64            // 2*N2 (re block + im block)
#define BL (B * L)      // 32768
#define QTR (CB / 4)    // 128 cb per corr block
#define NCQ (NCH / 4)   // 16 chunks per quarter
#define CBPQ 132        // padded locS row stride (floats)
#define XRP 132         // padded xrs row stride
#define STP 66          // stg row stride
#define NCC 4           // chunks per k_out block

typedef unsigned long long u64;

__device__ __forceinline__ u64 pk2(float lo, float hi) {
    u64 r; asm("mov.b64 %0, {%1, %2};" : "=l"(r) : "f"(lo), "f"(hi)); return r;
}
__device__ __forceinline__ float2 upk2(u64 v) {
    float2 f; asm("mov.b64 {%0, %1}, %2;" : "=f"(f.x), "=f"(f.y) : "l"(v)); return f;
}
__device__ __forceinline__ u64 fma2(u64 a, u64 b, u64 c) {
    u64 d; asm("fma.rn.f32x2 %0, %1, %2, %3;" : "=l"(d) : "l"(a), "l"(b), "l"(c)); return d;
}

// ---------------------------------------------------------------------------
// Device-global parameter / scratch arrays
// ---------------------------------------------------------------------------
__device__ float g_dATre[HN], g_dATim[HN];                  // dA^T (double-derived)
__device__ __align__(16) float g_E[Hd * T * Q];             // [h][tau][q]: dA^{T-1-tau} dB
__device__ __align__(16) float g_W[Hd * Q * T];             // [h][q][t]
__device__ float g_K[Hd * T];                               // conv kernel
__device__ __align__(16) float g_xT[(size_t)Hd * BL];       // transposed x: [h][b*L+t]
__device__ __align__(16) float g_loc[(size_t)Hd * Q * CB];  // [h][q][cb]
__device__ __align__(16) float g_corr[(size_t)Hd * CB * T]; // [h][cb][t]
__device__ float g_qre[HN * 32], g_qim[HN * 32];            // quarter carry-in states

// ---------------------------------------------------------------------------
// K0 (fused): per-h discretization, E table, W table (+transpose), K kernel.
// grid Hd, block 32 (one warp; lane = mode n).
// ---------------------------------------------------------------------------
__global__ void __launch_bounds__(32) k_prep(const float* __restrict__ log_dt,
                                             const float* __restrict__ arl,
                                             const float* __restrict__ aim,
                                             const float* __restrict__ Bre,
                                             const float* __restrict__ Bim,
                                             const float* __restrict__ Cre,
                                             const float* __restrict__ Cim) {
    __shared__ float wt[T * 68];   // [t][q]
    const int h = blockIdx.x;
    const int n = threadIdx.x;
    const int i = h * 32 + n;
    float dt   = expf(log_dt[h]);
    float are  = -expf(arl[i]);
    float aimv = aim[i];
    float zre = are * dt, zim = aimv * dt;
    float sz, cz; sincosf(zim, &sz, &cz);
    float ez = expf(zre);
    float dre = ez * cz, dimv = ez * sz;   // dA
    float sh = sinf(0.5f * zim);
    float em1re = expm1f(zre) * cz - 2.0f * sh * sh;
    float em1im = ez * sz;
    float inv = 1.0f / (are * are + aimv * aimv);
    float fre = (em1re * are + em1im * aimv) * inv;
    float fim = (em1im * are - em1re * aimv) * inv;
    float bre0 = Bre[i], bim0 = Bim[i];
    float dbre = bre0 * fre - bim0 * fim;
    float dbim = bre0 * fim + bim0 * fre;
    float c2re  =  2.0f * Cre[i];
    float c2imN = -2.0f * Cim[i];
    double zred = (double)are * (double)dt * (double)T;
    double zimd = (double)aimv * (double)dt * (double)T;
    double ezd = exp(zred);
    g_dATre[i] = (float)(ezd * cos(zimd));
    g_dATim[i] = (float)(ezd * sin(zimd));
    // E[tau] = dA^{T-1-tau} dB (reversed rows); W[t] = C dA^{t+1}; K[l]
    float pre = dbre, pim = dbim;
    float cre0 = Cre[i], cim0 = Cim[i];
    float wre = cre0 * dre - cim0 * dimv;
    float wim = cre0 * dimv + cim0 * dre;
    for (int l = 0; l < T; ++l) {
        g_E[((size_t)h * T + (T - 1 - l)) * Q + n]      = pre;
        g_E[((size_t)h * T + (T - 1 - l)) * Q + 32 + n] = pim;
        wt[l * 68 + n]      =  2.0f * wre;
        wt[l * 68 + 32 + n] = -2.0f * wim;
        float kl = fmaf(c2re, pre, c2imN * pim);
        kl += __shfl_xor_sync(0xffffffffu, kl, 1);
        kl += __shfl_xor_sync(0xffffffffu, kl, 2);
        kl += __shfl_xor_sync(0xffffffffu, kl, 4);
        kl += __shfl_xor_sync(0xffffffffu, kl, 8);
        kl += __shfl_xor_sync(0xffffffffu, kl, 16);
        if (n == 0) g_K[h * T + l] = kl;
        float tre = pre * dre - pim * dimv; pim = pre * dimv + pim * dre; pre = tre;
        float ure = wre * dre - wim * dimv; wim = wre * dimv + wim * dre; wre = ure;
    }
    __syncthreads();
    for (int k = n; k < Q * T / 4; k += 32) {
        int q = k >> 4, tq = (k & 15) * 4;
        float4 v = make_float4(wt[(tq + 0) * 68 + q], wt[(tq + 1) * 68 + q],
                               wt[(tq + 2) * 68 + q], wt[(tq + 3) * 68 + q]);
        *reinterpret_cast<float4*>(&g_W[((size_t)h * Q + q) * T + tq]) = v;
    }
}

// ---------------------------------------------------------------------------
// K-tr: transpose x [bt][h] -> xT [h][bt], 64x64 tiles, float4 global I/O
// ---------------------------------------------------------------------------
__global__ void __launch_bounds__(256) k_tr(const float* __restrict__ x) {
    __shared__ float tile[64 * 65];
    const int bt0 = blockIdx.x * 64;
    const int h0  = blockIdx.y * 64;
    const int tid = threadIdx.x;
    #pragma unroll
    for (int it = 0; it < 4; ++it) {
        int idx = tid + it * 256;           // [0,1024)
        int r = idx >> 4, q = idx & 15;
        float4 v = *reinterpret_cast<const float4*>(
            &x[(size_t)(bt0 + r) * Hd + h0 + q * 4]);
        float* tr = &tile[r * 65 + q * 4];
        tr[0] = v.x; tr[1] = v.y; tr[2] = v.z; tr[3] = v.w;
    }
    __syncthreads();
    #pragma unroll
    for (int it = 0; it < 4; ++it) {
        int idx = tid + it * 256;
        int hh = idx >> 4, rq = idx & 15;
        float4 v = make_float4(tile[(rq * 4 + 0) * 65 + hh],
                               tile[(rq * 4 + 1) * 65 + hh],
                               tile[(rq * 4 + 2) * 65 + hh],
                               tile[(rq * 4 + 3) * 65 + hh]);
        *reinterpret_cast<float4*>(&g_xT[(size_t)(h0 + hh) * BL + bt0 + rq * 4]) = v;
    }
}

// ---------------------------------------------------------------------------
// K1: loc[h][q][cb] = sum_tau E[h][tau][q] * x[cb][tau]
// 4 cb per lane, f32x2. grid (Hd, CB/128), block 256, dynamic smem.
// ---------------------------------------------------------------------------
__global__ void __launch_bounds__(256) k_loc() {
    extern __shared__ float sm[];
    float* Es  = sm;                // [64][64] 16KB
    float* xrs = sm + T * Q;        // [64][XRP] 33.8KB
    const int h = blockIdx.x;
    const int cb0 = blockIdx.y * 128;
    const int tid = threadIdx.x;
    for (int k = tid; k < T * Q / 4; k += 256)
        reinterpret_cast<float4*>(Es)[k] =
            reinterpret_cast<const float4*>(g_E + (size_t)h * T * Q)[k];
    for (int k = tid; k < 128 * T; k += 256) {
        int c2 = k >> 6, tau = k & 63;
        int cb = cb0 + c2, b = cb & 7, c = cb >> 3;
        xrs[tau * XRP + c2] = g_xT[(size_t)h * BL + b * L + c * T + tau];
    }
    __syncthreads();
    const int cc = tid & 31, w = tid >> 5, q0 = w * 8;
    u64 acc[4][4];
    #pragma unroll
    for (int a = 0; a < 4; ++a)
        #pragma unroll
        for (int p = 0; p < 4; ++p) acc[a][p] = 0ull;
    #pragma unroll 4
    for (int tau = 0; tau < T; ++tau) {
        float4 xv = *reinterpret_cast<const float4*>(&xrs[tau * XRP + cc * 4]);
        ulonglong2 ea = *reinterpret_cast<const ulonglong2*>(&Es[tau * Q + q0]);
        ulonglong2 eb = *reinterpret_cast<const ulonglong2*>(&Es[tau * Q + q0 + 4]);
        u64 xx;
        xx = pk2(xv.x, xv.x);
        acc[0][0] = fma2(ea.x, xx, acc[0][0]); acc[0][1] = fma2(ea.y, xx, acc[0][1]);
        acc[0][2] = fma2(eb.x, xx, acc[0][2]); acc[0][3] = fma2(eb.y, xx, acc[0][3]);
        xx = pk2(xv.y, xv.y);
        acc[1][0] = fma2(ea.x, xx, acc[1][0]); acc[1][1] = fma2(ea.y, xx, acc[1][1]);
        acc[1][2] = fma2(eb.x, xx, acc[1][2]); acc[1][3] = fma2(eb.y, xx, acc[1][3]);
        xx = pk2(xv.z, xv.z);
        acc[2][0] = fma2(ea.x, xx, acc[2][0]); acc[2][1] = fma2(ea.y, xx, acc[2][1]);
        acc[2][2] = fma2(eb.x, xx, acc[2][2]); acc[2][3] = fma2(eb.y, xx, acc[2][3]);
        xx = pk2(xv.w, xv.w);
        acc[3][0] = fma2(ea.x, xx, acc[3][0]); acc[3][1] = fma2(ea.y, xx, acc[3][1]);
        acc[3][2] = fma2(eb.x, xx, acc[3][2]); acc[3][3] = fma2(eb.y, xx, acc[3][3]);
    }
    #pragma unroll
    for (int p = 0; p < 4; ++p) {
        float2 f0 = upk2(acc[0][p]), f1 = upk2(acc[1][p]);
        float2 f2 = upk2(acc[2][p]), f3 = upk2(acc[3][p]);
        int q = q0 + 2 * p;
        *reinterpret_cast<float4*>(&g_loc[((size_t)h * Q + q) * CB + cb0 + cc * 4]) =
            make_float4(f0.x, f1.x, f2.x, f3.x);
        *reinterpret_cast<float4*>(&g_loc[((size_t)h * Q + q + 1) * CB + cb0 + cc * 4]) =
            make_float4(f0.y, f1.y, f2.y, f3.y);
    }
}

// ---------------------------------------------------------------------------
// K-mid: quarter-boundary carry states. Thread = (h, n, b); walks 48 chunk
// locals, stores the state after 16/32/48 chunks. Same fmaf order as the
// in-block scan => bit-identical carries.
// ---------------------------------------------------------------------------
__global__ void k_mid() {
    int i = blockIdx.x * 256 + threadIdx.x;   // [0, HN*8)
    if (i >= HN * 8) return;
    int b = i & 7, n = (i >> 3) & 31, h = i >> 8;
    float aRe = g_dATre[h * 32 + n], aIm = g_dATim[h * 32 + n];
    const float* gr = &g_loc[((size_t)h * Q + n) * CB + b];
    const float* gi = &g_loc[((size_t)h * Q + 32 + n) * CB + b];
    float cre = 0.0f, cim = 0.0f;
    #pragma unroll
    for (int qi = 0; qi < 3; ++qi) {
        #pragma unroll
        for (int c = 0; c < NCQ; ++c) {
            float lre = __ldg(gr + (qi * NCQ + c) * 8);
            float lim = __ldg(gi + (qi * NCQ + c) * 8);
            float nre = fmaf(aRe, cre, fmaf(-aIm, cim, lre));
            float nim = fmaf(aIm, cre, fmaf(aRe, cim, lim));
            cre = nre; cim = nim;
        }
        g_qre[(h * 32 + n) * 32 + qi * 8 + b] = cre;
        g_qim[(h * 32 + n) * 32 + qi * 8 + b] = cim;
    }
}

// ---------------------------------------------------------------------------
// K2: carry-scan (16 chunks) + correction GEMM per quarter.
// grid (Hd, 4), block 256. smem: locS [Q][CBPQ] + Ws [Q][T] + stg [64][STP].
// ---------------------------------------------------------------------------
__global__ void __launch_bounds__(256) k_corrf(float* __restrict__ out, int stateMode) {
    extern __shared__ float sm[];
    float* locS = sm;                    // 64*132 = 33.8KB
    float* Ws   = sm + Q * CBPQ;         // 16KB
    float* stg  = Ws + Q * T;            // 64*66 = 16.9KB
    const int h = blockIdx.x;
    const int qtr = blockIdx.y;
    const int cbh = qtr * QTR;
    const int tid = threadIdx.x;
    for (int k = tid; k < Q * T / 4; k += 256)
        reinterpret_cast<float4*>(Ws)[k] =
            reinterpret_cast<const float4*>(g_W + (size_t)h * Q * T)[k];
    for (int k = tid; k < Q * QTR / 4; k += 256) {
        int q = k >> 5, c4 = k & 31;
        *reinterpret_cast<float4*>(&locS[q * CBPQ + c4 * 4]) =
            *reinterpret_cast<const float4*>(&g_loc[((size_t)h * Q + q) * CB + cbh + c4 * 4]);
    }
    __syncthreads();
    // exclusive carry scan over this quarter's 16 chunks, in place; thread = (n, b)
    {
        int n = tid >> 3, b = tid & 7;
        float aRe = g_dATre[h * 32 + n], aIm = g_dATim[h * 32 + n];
        float cre = 0.0f, cim = 0.0f;
        if (qtr > 0) {
            cre = g_qre[(h * 32 + n) * 32 + (qtr - 1) * 8 + b];
            cim = g_qim[(h * 32 + n) * 32 + (qtr - 1) * 8 + b];
        }
        float* pr = &locS[n * CBPQ + b];
        float* pi = &locS[(32 + n) * CBPQ + b];
        #pragma unroll 4
        for (int c = 0; c < NCQ; ++c) {
            float lre = pr[c * 8], lim = pi[c * 8];
            pr[c * 8] = cre; pi[c * 8] = cim;
            float nre = fmaf(aRe, cre, fmaf(-aIm, cim, lre));
            float nim = fmaf(aIm, cre, fmaf(aRe, cim, lim));
            cre = nre; cim = nim;
        }
        if (qtr == 3 && stateMode > 0) {
            size_t ysEnd = (size_t)B * L * Hd;
            size_t idx = ((size_t)b * Hd + h) * N2 + n;
            out[ysEnd + idx] = cre;
            if (stateMode > 1) out[ysEnd + (size_t)B * Hd * N2 + idx] = cim;
        }
    }
    __syncthreads();
    // correction GEMM: corr[cb][t] = sum_q W[q][t] * s0[q][cb]  (single pass)
    const int cc = tid & 31, w = tid >> 5, t0 = w * 8;
    u64 acc[4][4];
    #pragma unroll
    for (int a = 0; a < 4; ++a)
        #pragma unroll
        for (int p = 0; p < 4; ++p) acc[a][p] = 0ull;
    #pragma unroll 4
    for (int q = 0; q < Q; ++q) {
        float4 sv = *reinterpret_cast<const float4*>(&locS[q * CBPQ + cc * 4]);
        ulonglong2 wa = *reinterpret_cast<const ulonglong2*>(&Ws[q * T + t0]);
        ulonglong2 wb = *reinterpret_cast<const ulonglong2*>(&Ws[q * T + t0 + 4]);
        u64 xx;
        xx = pk2(sv.x, sv.x);
        acc[0][0] = fma2(wa.x, xx, acc[0][0]); acc[0][1] = fma2(wa.y, xx, acc[0][1]);
        acc[0][2] = fma2(wb.x, xx, acc[0][2]); acc[0][3] = fma2(wb.y, xx, acc[0][3]);
        xx = pk2(sv.y, sv.y);
        acc[1][0] = fma2(wa.x, xx, acc[1][0]); acc[1][1] = fma2(wa.y, xx, acc[1][1]);
        acc[1][2] = fma2(wb.x, xx, acc[1][2]); acc[1][3] = fma2(wb.y, xx, acc[1][3]);
        xx = pk2(sv.z, sv.z);
        acc[2][0] = fma2(wa.x, xx, acc[2][0]); acc[2][1] = fma2(wa.y, xx, acc[2][1]);
        acc[2][2] = fma2(wb.x, xx, acc[2][2]); acc[2][3] = fma2(wb.y, xx, acc[2][3]);
        xx = pk2(sv.w, sv.w);
        acc[3][0] = fma2(wa.x, xx, acc[3][0]); acc[3][1] = fma2(wa.y, xx, acc[3][1]);
        acc[3][2] = fma2(wb.x, xx, acc[3][2]); acc[3][3] = fma2(wb.y, xx, acc[3][3]);
    }
    // two store rounds through the 64-row staging buffer
    #pragma unroll
    for (int rnd = 0; rnd < 2; ++rnd) {
        if ((cc >> 4) == rnd) {
            #pragma unroll
            for (int a = 0; a < 4; ++a) {
                float* row = &stg[(cc * 4 + a - rnd * 64) * STP + t0];
                #pragma unroll
                for (int p = 0; p < 4; ++p) {
                    float2 f = upk2(acc[a][p]);
                    *reinterpret_cast<float2*>(&row[2 * p]) = f;
                }
            }
        }
        __syncthreads();
        for (int k = tid; k < 64 * T / 4; k += 256) {
            int r = k >> 4, tp = (k & 15) * 4;
            float2 a2 = *reinterpret_cast<const float2*>(&stg[r * STP + tp]);
            float2 b2 = *reinterpret_cast<const float2*>(&stg[r * STP + tp + 2]);
            *reinterpret_cast<float4*>(
                &g_corr[((size_t)h * CB + cbh + rnd * 64 + r) * T + tp]) =
                make_float4(a2.x, a2.y, b2.x, b2.y);
        }
        __syncthreads();
    }
}

// ---------------------------------------------------------------------------
// K4: output = causal conv(K,x) + corr + D*x, then exact GELU.
// NCC chunks per block. grid (CB/NCC, Hd/32), block 256
// ---------------------------------------------------------------------------
__global__ void __launch_bounds__(256) k_out(const float* __restrict__ x,
                                             const float* __restrict__ Dv,
                                             float* __restrict__ out) {
    __shared__ float xs[32 * 133];
    __shared__ float Ks[32 * 65];
    __shared__ float cs[32 * 65];
    const int h0 = blockIdx.y * 32;
    const int tid = threadIdx.x;
    const int hh = tid & 31, w = tid >> 5, t0 = w * 8;
    for (int k = tid; k < 32 * 63; k += 256) {
        int h2 = k & 31, r = k >> 5;
        xs[h2 * 133 + r] = 0.0f;
    }
    for (int k = tid; k < 32 * 64; k += 256) {
        int h2 = k & 31, l = k >> 5;
        Ks[h2 * 65 + l] = g_K[(h0 + h2) * T + l];
    }
    const float Dh = Dv[h0 + hh];
    const float* xrow = &xs[hh * 133];
    const float* krow = &Ks[hh * 65];

    for (int ci = 0; ci < NCC; ++ci) {
        const int cb = blockIdx.x * NCC + ci;
        const int b = cb & 7, c = cb >> 3;
        __syncthreads();
        for (int k = tid; k < 32 * 64; k += 256) {
            int h2 = k & 31, tt = k >> 5;
            xs[h2 * 133 + 63 + tt] = x[((size_t)b * L + c * T + tt) * Hd + h0 + h2];
        }
        for (int k = tid; k < 2048; k += 256) {
            int h2 = k >> 6, tt = k & 63;
            cs[h2 * 65 + tt] = g_corr[((size_t)(h0 + h2) * CB + cb) * T + tt];
        }
        __syncthreads();

        u64 accp[4];
        #pragma unroll
        for (int p = 0; p < 4; ++p)
            accp[p] = pk2(cs[hh * 65 + t0 + 2 * p], cs[hh * 65 + t0 + 2 * p + 1]);

        for (int lt = 0; lt <= w; ++lt) {
            const int l0 = lt * 8;
            const int rb = 63 + t0 - l0 - 7;
            float xw[15];
            #pragma unroll
            for (int j = 0; j < 15; ++j) xw[j] = xrow[rb + j];
            u64 xwp[14];
            #pragma unroll
            for (int a = 0; a < 14; ++a) xwp[a] = pk2(xw[a], xw[a + 1]);
            #pragma unroll
            for (int i = 0; i < 8; ++i) {
                float kv = krow[l0 + i];
                u64 k2 = pk2(kv, kv);
                accp[0] = fma2(k2, xwp[7 - i], accp[0]);
                accp[1] = fma2(k2, xwp[9 - i], accp[1]);
                accp[2] = fma2(k2, xwp[11 - i], accp[2]);
                accp[3] = fma2(k2, xwp[13 - i], accp[3]);
            }
        }

        float acc[8];
        #pragma unroll
        for (int p = 0; p < 4; ++p) {
            float2 f = upk2(accp[p]);
            acc[2 * p] = f.x; acc[2 * p + 1] = f.y;
        }
        #pragma unroll
        for (int j = 0; j < 8; ++j) {
            float xv = xrow[63 + t0 + j];
            float yv = fmaf(Dh, xv, acc[j]);
            float g = 0.5f * yv * (1.0f + erff(yv * 0.70710678118654752f));
            out[((size_t)b * L + c * T + t0 + j) * Hd + h0 + hh] = g;
        }
    }
}

// ---------------------------------------------------------------------------
// Launch
// ---------------------------------------------------------------------------
extern "C" void kernel_launch(void* const* d_in, const int* in_sizes, int n_in,
                              void* d_out, int out_size) {
    const float* x      = (const float*)d_in[0];
    const float* log_dt = (const float*)d_in[1];
    const float* arl    = (const float*)d_in[2];
    const float* aim    = (const float*)d_in[3];
    const float* Bre    = (const float*)d_in[4];
    const float* Bim    = (const float*)d_in[5];
    const float* Cre    = (const float*)d_in[6];
    const float* Cim    = (const float*)d_in[7];
    const float* Dv     = (const float*)d_in[8];
    float* out = (float*)d_out;

    const long long ysElems = (long long)B * L * Hd;   // 16,777,216
    const long long stN     = (long long)B * Hd * N2;  // 131,072
    int stateMode = 0;
    if ((long long)out_size >= ysElems + 2 * stN) stateMode = 2;
    else if ((long long)out_size >= ysElems + stN) stateMode = 1;

    const int locSmem  = (T * Q + T * XRP) * 4;                 // 50,176 B
    const int corrSmem = (Q * CBPQ + Q * T + 64 * STP) * 4;     // 67,072 B
    static int attrDone = 0;
    if (!attrDone) {
        cudaFuncSetAttribute(k_loc, cudaFuncAttributeMaxDynamicSharedMemorySize, locSmem);
        cudaFuncSetAttribute(k_corrf, cudaFuncAttributeMaxDynamicSharedMemorySize, corrSmem);
        attrDone = 1;
    }

    k_prep<<<Hd, 32>>>(log_dt, arl, aim, Bre, Bim, Cre, Cim);
    k_tr<<<dim3(BL / 64, Hd / 64), 256>>>(x);
    k_loc<<<dim3(Hd, CB / 128), 256, locSmem>>>();
    k_mid<<<(HN * 8 + 255) / 256, 256>>>();
    k_corrf<<<dim3(Hd, 4), 256, corrSmem>>>(out, stateMode);
    k_out<<<dim3(CB / NCC, Hd / 32), 256>>>(x, Dv, out);
}